// round 10
// baseline (speedup 1.0000x reference)
#include <cuda_runtime.h>
#include <math.h>

#define SS 256
#define BB 64
#define HH 512
#define EE 300
#define TT 10
#define G4 2048   // 4*H

// ---------------- scratch (static device memory; no allocations) ----------------
__device__ float g_xw2[2][SS][G4][BB];     // input projections, [dir][s][col][b] (268 MB)
__device__ float g_hbk[SS][2][BB][HH];     // h outputs [s][dir][b][k] for K3 (134 MB)
__device__ float g_ht[2][2][HH][BB];       // [dir][parity][k][b] k-major carry (L2-hot)
__device__ float g_c[2][HH][BB];           // c carry [dir][u][b]
__device__ float g_wp[2][HH][G4];          // permuted whh: [d][k][(u>>1)*8+q*2+(u&1)] (8 MB)
__device__ float g_feats[BB][SS][TT];      // emissions

__device__ __forceinline__ float sigmf(float x) { return 1.0f / (1.0f + expf(-x)); }

// ---- packed f32x2 helpers (FFMA2: 2 independent fp32 FMAs, bit-exact) ----
__device__ __forceinline__ unsigned long long pack2(float lo, float hi) {
    unsigned long long r;
    asm("mov.b64 %0, {%1, %2};" : "=l"(r) : "f"(lo), "f"(hi));
    return r;
}
__device__ __forceinline__ void fma2(unsigned long long& d, unsigned long long a, unsigned long long b) {
    asm("fma.rn.f32x2 %0, %1, %2, %0;" : "+l"(d) : "l"(a), "l"(b));
}
__device__ __forceinline__ float2 unpack2(unsigned long long v) {
    float lo, hi;
    asm("mov.b64 {%0, %1}, %2;" : "=f"(lo), "=f"(hi) : "l"(v));
    return make_float2(lo, hi);
}
__device__ __forceinline__ unsigned int smem_u32(const void* p) {
    unsigned int a;
    asm("{ .reg .u64 t; cvta.to.shared.u64 t, %1; cvt.u32.u64 %0, t; }" : "=r"(a) : "l"(p));
    return a;
}
__device__ __forceinline__ void cpa16(unsigned int dst, const void* src) {
    asm volatile("cp.async.cg.shared.global [%0], [%1], 16;" :: "r"(dst), "l"(src));
}

// ---------------- K0: permute recurrent weights ----------------
// g_wp[d][k][(u>>1)*8 + q*2 + (u&1)] = whh_d[q*HH + u][k]
__global__ void k0_prep(const float* __restrict__ whh_f, const float* __restrict__ whh_b) {
    const int d = blockIdx.x;
    const int k = blockIdx.y;
    const int u = threadIdx.x;    // 0..511
    const float* w = d ? whh_b : whh_f;
    const int colb = (u >> 1) * 8 + (u & 1);
#pragma unroll
    for (int q = 0; q < 4; q++)
        g_wp[d][k][colb + q * 2] = w[(q * HH + u) * HH + k];
}

// ---------------- K1: fused embedding gather + input projection GEMM ----------------
__global__ __launch_bounds__(256) void k1_proj(
    const int* __restrict__ tokens, const float* __restrict__ emb,
    const float* __restrict__ wih_f, const float* __restrict__ b_f,
    const float* __restrict__ wih_b, const float* __restrict__ b_b)
{
    __shared__ float As[20][68];   // [k][m-local]
    __shared__ float Bs[20][68];   // [k][n-local]

    const int tid = threadIdx.x;
    const int tx = tid & 15, ty = tid >> 4;
    const int n0 = blockIdx.x * 64;
    const int m0 = blockIdx.y * 64;

    const int arow = tid >> 2;            // 0..63
    const int akk  = (tid & 3) * 5;       // 0,5,10,15
    const int m_g  = m0 + arow;
    const int s_g  = m_g >> 6, b_g = m_g & 63;
    int tok = tokens[b_g * SS + s_g];
    if (tok < 0 || tok >= 30000) tok = 0;
    const float* asrc = emb + (long)tok * EE;

    const int bg = n0 + arow;
    const float* wsrc = (bg < G4) ? (wih_f + (long)bg * EE)
                                  : (wih_b + (long)(bg - G4) * EE);

    unsigned long long accp[2][4] = {};

    for (int kt = 0; kt < 15; ++kt) {     // K = 300 = 15 * 20
        const int k0 = kt * 20;
#pragma unroll
        for (int l = 0; l < 5; l++) As[akk + l][arow] = asrc[k0 + akk + l];
#pragma unroll
        for (int l = 0; l < 5; l++) Bs[akk + l][arow] = wsrc[k0 + akk + l];
        __syncthreads();
#pragma unroll
        for (int k = 0; k < 20; k++) {
            ulonglong2 ap = *(const ulonglong2*)&As[k][ty * 4];
            float4 bv = *(const float4*)&Bs[k][tx * 4];
            unsigned long long bp0 = pack2(bv.x, bv.x);
            unsigned long long bp1 = pack2(bv.y, bv.y);
            unsigned long long bp2 = pack2(bv.z, bv.z);
            unsigned long long bp3 = pack2(bv.w, bv.w);
            fma2(accp[0][0], ap.x, bp0); fma2(accp[0][1], ap.x, bp1);
            fma2(accp[0][2], ap.x, bp2); fma2(accp[0][3], ap.x, bp3);
            fma2(accp[1][0], ap.y, bp0); fma2(accp[1][1], ap.y, bp1);
            fma2(accp[1][2], ap.y, bp2); fma2(accp[1][3], ap.y, bp3);
        }
        __syncthreads();
    }

    // epilogue: write g_xw2[dir][s][col(u,q)][b]
#pragma unroll
    for (int j = 0; j < 4; j++) {
        const int g   = n0 + tx * 4 + j;
        const int dir = g >> 11;
        const int gl  = g & 2047;
        const int q   = gl >> 9;
        const int u   = gl & 511;
        const int col = (u >> 1) * 8 + q * 2 + (u & 1);
        const float bias = dir ? b_b[gl] : b_f[gl];
#pragma unroll
        for (int p = 0; p < 2; p++) {
            float2 v = unpack2(accp[p][j]);
            const int mA = m0 + ty * 4 + 2 * p;
            g_xw2[dir][mA >> 6][col][mA & 63]             = v.x + bias;
            g_xw2[dir][(mA + 1) >> 6][col][(mA + 1) & 63] = v.y + bias;
        }
    }
}

// ---------------- K2: one LSTM time step (K-split, cp.async, 4 CTAs/SM) ----------------
// grid 512: bx>>8 = dir, bx&255 = unit-pair p (u0 = 2p). 128 threads:
// kh = tid>>6 selects K half [0,256) / [256,512); b = tid&63.
// Each half streams its own 32-k tiles (h k-major from g_ht, weights from g_wp)
// via cp.async double buffering. FFMA2 accumulates (u0,u0+1) per gate; halves
// reduced through smem (fixed order -> deterministic), kh=0 does the cell update.
__global__ __launch_bounds__(128, 4) void k2_step(const int* __restrict__ lengths, int t)
{
    __shared__ float hs[2][2][32][68];   // [kh][buf][k][b]  34.8 KB
    __shared__ float sw[2][2][32][8];    // [kh][buf][k][col] 4 KB
    __shared__ float red[64][9];         // cross-half partials (pad 9: conflict-free)

    const int bx  = blockIdx.x;
    const int dir = bx >> 8;
    const int p   = bx & 255;            // unit pair 0..255
    const int s   = dir ? (SS - 1 - t) : t;
    const int tid = threadIdx.x;
    const int kh  = tid >> 6;            // K half
    const int j   = tid & 63;            // lane-in-half = batch b
    const int u0  = p * 2;

    const int len = lengths[j];

    // xw gates (kh==0 only; coalesced over b)
    float xwv[8];
    if (kh == 0) {
        const float* xp = &g_xw2[dir][s][p * 8][j];
#pragma unroll
        for (int i = 0; i < 8; i++) xwv[i] = __ldg(&xp[i * BB]);
    }

    unsigned long long accI = 0, accF = 0, accG = 0, accO = 0;   // (u0, u0+1)

    if (t > 0) {
        const int rp = (t & 1) ^ 1;
        const int kb = kh * 256;                                      // K-half base
        const float* __restrict__ hbase = &g_ht[dir][rp][kb][0];      // contiguous rows
        const float* __restrict__ wsrc  = &g_wp[dir][0][p * 8];       // row stride G4

        const unsigned int hs_s = smem_u32(&hs[kh][0][0][0]);
        const unsigned int sw_s = smem_u32(&sw[kh][0][0][0]);
        const unsigned int HBUF = 32 * 68 * 4;   // bytes per hs buffer
        const unsigned int WBUF = 32 * 8 * 4;

        // stage tile kt into buffer bf
        auto stage = [&](int kt, int bf) {
            // h tile: contiguous 8 KB; 64 threads x 8 cpa16
            const float* hsrc = hbase + kt * 32 * BB;
            const unsigned int hd = hs_s + bf * HBUF;
#pragma unroll
            for (int l = 0; l < 8; l++) {
                const int chunk = j + l * 64;               // 16B chunks
                const int r = chunk >> 4, c = (chunk & 15) * 4;
                cpa16(hd + (r * 68 + c) * 4, hsrc + chunk * 4);
            }
            // w tile: 32 rows x 32B; thread j covers row j>>1, half (j&1)
            {
                const int r = j >> 1, c = (j & 1) * 4;
                cpa16(sw_s + bf * WBUF + (r * 8 + c) * 4,
                      wsrc + (long)(kb + kt * 32 + r) * G4 + c);
            }
        };

        stage(0, 0);
        asm volatile("cp.async.commit_group;");

        int cb = 0;
        for (int kt = 0; kt < 8; ++kt) {          // 256 k per half = 8 * 32
            if (kt < 7) {
                stage(kt + 1, cb ^ 1);
                asm volatile("cp.async.commit_group;");
                asm volatile("cp.async.wait_group 1;");
            } else {
                asm volatile("cp.async.wait_group 0;");
            }
            __syncthreads();
#pragma unroll
            for (int k = 0; k < 32; k++) {
                const float h = hs[kh][cb][k][j];                         // 1-wf LDS
                const unsigned long long hp = pack2(h, h);
                ulonglong2 w01 = *(const ulonglong2*)&sw[kh][cb][k][0];   // broadcast
                ulonglong2 w23 = *(const ulonglong2*)&sw[kh][cb][k][4];
                fma2(accI, w01.x, hp);
                fma2(accF, w01.y, hp);
                fma2(accG, w23.x, hp);
                fma2(accO, w23.y, hp);
            }
            __syncthreads();                       // protect cb before restaging
            cb ^= 1;
        }
    }

    // cross-half reduction (fixed order: half0 + half1 -> deterministic)
    {
        const float2 ai = unpack2(accI), af = unpack2(accF);
        const float2 ag = unpack2(accG), ao = unpack2(accO);
        if (kh == 1) {
            red[j][0] = ai.x; red[j][1] = ai.y;
            red[j][2] = af.x; red[j][3] = af.y;
            red[j][4] = ag.x; red[j][5] = ag.y;
            red[j][6] = ao.x; red[j][7] = ao.y;
        }
        __syncthreads();
        if (kh == 0) {
            const float i0 = (ai.x + red[j][0]) + xwv[0];
            const float i1 = (ai.y + red[j][1]) + xwv[1];
            const float f0 = (af.x + red[j][2]) + xwv[2];
            const float f1 = (af.y + red[j][3]) + xwv[3];
            const float g0 = (ag.x + red[j][4]) + xwv[4];
            const float g1 = (ag.y + red[j][5]) + xwv[5];
            const float o0 = (ao.x + red[j][6]) + xwv[6];
            const float o1 = (ao.y + red[j][7]) + xwv[7];

            float c_old0 = 0.f, c_old1 = 0.f;
            if (t > 0) {
                c_old0 = g_c[dir][u0][j];
                c_old1 = g_c[dir][u0 + 1][j];
            }
            const float cn0 = sigmf(f0) * c_old0 + sigmf(i0) * tanhf(g0);
            const float hn0 = sigmf(o0) * tanhf(cn0);
            const float cn1 = sigmf(f1) * c_old1 + sigmf(i1) * tanhf(g1);
            const float hn1 = sigmf(o1) * tanhf(cn1);

            const bool msk = s < len;
            const float hw0 = msk ? hn0 : 0.f;
            const float hw1 = msk ? hn1 : 0.f;
            g_c[dir][u0][j]     = msk ? cn0 : c_old0;
            g_c[dir][u0 + 1][j] = msk ? cn1 : c_old1;
            const int wp = t & 1;
            g_ht[dir][wp][u0][j]     = hw0;         // coalesced k-major carry
            g_ht[dir][wp][u0 + 1][j] = hw1;
            *(float2*)&g_hbk[s][dir][j][u0] = make_float2(hw0, hw1);   // K3 layout
        }
    }
}

// ---------------- K3: emissions feats = h @ w_out^T + b_out ----------------
__global__ __launch_bounds__(256) void k3_feats(
    const float* __restrict__ w_out, const float* __restrict__ b_out)
{
    __shared__ float ws[TT * 1024];   // [t][dir*512 + k]
    for (int i = threadIdx.x; i < TT * 1024; i += 256) ws[i] = w_out[i];
    __syncthreads();

    const int widx = blockIdx.x * 8 + (threadIdx.x >> 5);
    const int lane = threadIdx.x & 31;
    const int s = widx >> 6, b = widx & 63;

    float acc[TT];
#pragma unroll
    for (int t = 0; t < TT; t++) acc[t] = 0.0f;

#pragma unroll
    for (int d = 0; d < 2; d++) {
        const float* hrow = &g_hbk[s][d][b][0];
#pragma unroll 4
        for (int i = 0; i < 16; i++) {
            const int k = lane + i * 32;
            const float hv = hrow[k];
#pragma unroll
            for (int t = 0; t < TT; t++) acc[t] += hv * ws[t * 1024 + d * 512 + k];
        }
    }
#pragma unroll
    for (int t = 0; t < TT; t++) {
        float v = acc[t];
        v += __shfl_xor_sync(0xffffffffu, v, 16);
        v += __shfl_xor_sync(0xffffffffu, v, 8);
        v += __shfl_xor_sync(0xffffffffu, v, 4);
        v += __shfl_xor_sync(0xffffffffu, v, 2);
        v += __shfl_xor_sync(0xffffffffu, v, 1);
        if (lane == t) g_feats[b][s][t] = v + b_out[t];
    }
}

// ---------------- K4: Viterbi decode + backtrace (one warp per batch) ----------------
// Output written as float32 (harness __output__ dtype).
__global__ __launch_bounds__(32) void k4_viterbi(
    const float* __restrict__ start_t, const float* __restrict__ end_t,
    const float* __restrict__ trans, const int* __restrict__ lengths,
    float* __restrict__ out)
{
    const int b = blockIdx.x;
    const int lane = threadIdx.x;
    __shared__ float fe[SS][TT];
    __shared__ float tr[TT][TT];
    __shared__ float sc[TT];
    __shared__ unsigned char bp[SS][TT];

    for (int i = lane; i < SS * TT; i += 32)
        ((float*)fe)[i] = ((const float*)g_feats[b])[i];
    for (int i = lane; i < TT * TT; i += 32)
        ((float*)tr)[i] = trans[i];
    int len = lengths[b];
    if (len < 0) len = 0; if (len > SS) len = SS;
    __syncwarp();
    if (lane < TT) sc[lane] = start_t[lane] + fe[0][lane];
    __syncwarp();

    for (int s = 1; s < SS; ++s) {
        float best = -1e30f; int arg = 0;
        if (lane < TT) {
#pragma unroll
            for (int i = 0; i < TT; i++) {
                const float c = sc[i] + tr[i][lane];
                if (c > best) { best = c; arg = i; }   // first-max, matches jnp.argmax
            }
        }
        __syncwarp();
        if (lane < TT) {
            if (s < len) { sc[lane] = best + fe[s][lane]; bp[s][lane] = (unsigned char)arg; }
            else         { bp[s][lane] = (unsigned char)lane; }
        }
        __syncwarp();
    }

    if (lane == 0) {
        float bestv = -1e30f; int last = 0;
        for (int j = 0; j < TT; j++) {
            const float v = sc[j] + end_t[j];
            if (v > bestv) { bestv = v; last = j; }
        }
        int cur = last;
        for (int s = SS - 1; s >= 1; --s) {
            out[b * SS + s] = (float)((s < len) ? cur : 0);
            cur = bp[s][cur];
        }
        out[b * SS + 0] = (float)cur;
    }
}

// ---------------- host ----------------
static int find_slot(const int* sz, int n, int want, int which, int fallback) {
    int seen = 0;
    for (int i = 0; i < n; i++)
        if (sz[i] == want) { if (seen == which) return i; seen++; }
    return fallback;
}

extern "C" void kernel_launch(void* const* d_in, const int* in_sizes, int n_in,
                              void* d_out, int out_size)
{
    const int i_tok  = find_slot(in_sizes, n_in, SS * BB,      0, 0);
    const int i_len  = find_slot(in_sizes, n_in, BB,           0, 1);
    const int i_emb  = find_slot(in_sizes, n_in, 30000 * EE,   0, 2);
    const int i_wif  = find_slot(in_sizes, n_in, G4 * EE,      0, 3);
    const int i_whf  = find_slot(in_sizes, n_in, G4 * HH,      0, 4);
    const int i_bf   = find_slot(in_sizes, n_in, G4,           0, 5);
    const int i_wib  = find_slot(in_sizes, n_in, G4 * EE,      1, 6);
    const int i_whb  = find_slot(in_sizes, n_in, G4 * HH,      1, 7);
    const int i_bb   = find_slot(in_sizes, n_in, G4,           1, 8);
    const int i_wout = find_slot(in_sizes, n_in, TT * 2 * HH,  0, 9);
    const int i_bout = find_slot(in_sizes, n_in, TT,           0, 10);
    const int i_st   = find_slot(in_sizes, n_in, TT,           1, 11);
    const int i_en   = find_slot(in_sizes, n_in, TT,           2, 12);
    const int i_tr   = find_slot(in_sizes, n_in, TT * TT,      0, 13);

    const int*   tokens  = (const int*)  d_in[i_tok];
    const int*   lens    = (const int*)  d_in[i_len];
    const float* emb     = (const float*)d_in[i_emb];
    const float* wih_f   = (const float*)d_in[i_wif];
    const float* whh_f   = (const float*)d_in[i_whf];
    const float* b_f     = (const float*)d_in[i_bf];
    const float* wih_b   = (const float*)d_in[i_wib];
    const float* whh_b   = (const float*)d_in[i_whb];
    const float* b_b     = (const float*)d_in[i_bb];
    const float* w_out   = (const float*)d_in[i_wout];
    const float* b_out   = (const float*)d_in[i_bout];
    const float* start_t = (const float*)d_in[i_st];
    const float* end_t   = (const float*)d_in[i_en];
    const float* trans   = (const float*)d_in[i_tr];
    float* out = (float*)d_out;

    k0_prep<<<dim3(2, HH), HH>>>(whh_f, whh_b);
    k1_proj<<<dim3(64, 256), 256>>>(tokens, emb, wih_f, b_f, wih_b, b_b);
    for (int t = 0; t < SS; ++t)
        k2_step<<<512, 128>>>(lens, t);
    k3_feats<<<2048, 256>>>(w_out, b_out);
    k4_viterbi<<<64, 32>>>(start_t, end_t, trans, lens, out);
}

// round 11
// speedup vs baseline: 1.1864x; 1.1864x over previous
#include <cuda_runtime.h>
#include <math.h>

#define SS 256
#define BB 64
#define HH 512
#define EE 300
#define TT 10
#define G4 2048   // 4*H

// ---------------- scratch (static device memory; no allocations) ----------------
__device__ float g_xw2[2][SS][G4][BB];     // input projections, [dir][s][col][b] (268 MB)
__device__ float g_hbk[SS][2][BB][HH];     // h outputs [s][dir][b][k] for K3 (134 MB)
__device__ float g_ht[2][2][HH][BB];       // [dir][parity][k][b] k-major carry (L2-hot)
__device__ float g_c[2][HH][BB];           // c carry [dir][u][b]
__device__ float g_wp[2][HH][G4];          // permuted whh: [d][k][(u>>1)*8+q*2+(u&1)] (8 MB)
__device__ float g_feats[BB][SS][TT];      // emissions

__device__ __forceinline__ float sigmf(float x) { return 1.0f / (1.0f + expf(-x)); }

// ---- packed f32x2 helpers (FFMA2: 2 independent fp32 FMAs, bit-exact) ----
__device__ __forceinline__ unsigned long long pack2(float lo, float hi) {
    unsigned long long r;
    asm("mov.b64 %0, {%1, %2};" : "=l"(r) : "f"(lo), "f"(hi));
    return r;
}
__device__ __forceinline__ void fma2(unsigned long long& d, unsigned long long a, unsigned long long b) {
    asm("fma.rn.f32x2 %0, %1, %2, %0;" : "+l"(d) : "l"(a), "l"(b));
}
__device__ __forceinline__ float2 unpack2(unsigned long long v) {
    float lo, hi;
    asm("mov.b64 {%0, %1}, %2;" : "=f"(lo), "=f"(hi) : "l"(v));
    return make_float2(lo, hi);
}

// ---------------- K0: permute recurrent weights ----------------
// g_wp[d][k][(u>>1)*8 + q*2 + (u&1)] = whh_d[q*HH + u][k]
__global__ void k0_prep(const float* __restrict__ whh_f, const float* __restrict__ whh_b) {
    const int d = blockIdx.x;
    const int k = blockIdx.y;
    const int u = threadIdx.x;    // 0..511
    const float* w = d ? whh_b : whh_f;
    const int colb = (u >> 1) * 8 + (u & 1);
#pragma unroll
    for (int q = 0; q < 4; q++)
        g_wp[d][k][colb + q * 2] = w[(q * HH + u) * HH + k];
}

// ---------------- K1: fused embedding gather + input projection GEMM ----------------
__global__ __launch_bounds__(256) void k1_proj(
    const int* __restrict__ tokens, const float* __restrict__ emb,
    const float* __restrict__ wih_f, const float* __restrict__ b_f,
    const float* __restrict__ wih_b, const float* __restrict__ b_b)
{
    __shared__ float As[20][68];   // [k][m-local]
    __shared__ float Bs[20][68];   // [k][n-local]

    const int tid = threadIdx.x;
    const int tx = tid & 15, ty = tid >> 4;
    const int n0 = blockIdx.x * 64;
    const int m0 = blockIdx.y * 64;

    const int arow = tid >> 2;            // 0..63
    const int akk  = (tid & 3) * 5;       // 0,5,10,15
    const int m_g  = m0 + arow;
    const int s_g  = m_g >> 6, b_g = m_g & 63;
    int tok = tokens[b_g * SS + s_g];
    if (tok < 0 || tok >= 30000) tok = 0;
    const float* asrc = emb + (long)tok * EE;

    const int bg = n0 + arow;
    const float* wsrc = (bg < G4) ? (wih_f + (long)bg * EE)
                                  : (wih_b + (long)(bg - G4) * EE);

    unsigned long long accp[2][4] = {};

    for (int kt = 0; kt < 15; ++kt) {     // K = 300 = 15 * 20
        const int k0 = kt * 20;
#pragma unroll
        for (int l = 0; l < 5; l++) As[akk + l][arow] = asrc[k0 + akk + l];
#pragma unroll
        for (int l = 0; l < 5; l++) Bs[akk + l][arow] = wsrc[k0 + akk + l];
        __syncthreads();
#pragma unroll
        for (int k = 0; k < 20; k++) {
            ulonglong2 ap = *(const ulonglong2*)&As[k][ty * 4];
            float4 bv = *(const float4*)&Bs[k][tx * 4];
            unsigned long long bp0 = pack2(bv.x, bv.x);
            unsigned long long bp1 = pack2(bv.y, bv.y);
            unsigned long long bp2 = pack2(bv.z, bv.z);
            unsigned long long bp3 = pack2(bv.w, bv.w);
            fma2(accp[0][0], ap.x, bp0); fma2(accp[0][1], ap.x, bp1);
            fma2(accp[0][2], ap.x, bp2); fma2(accp[0][3], ap.x, bp3);
            fma2(accp[1][0], ap.y, bp0); fma2(accp[1][1], ap.y, bp1);
            fma2(accp[1][2], ap.y, bp2); fma2(accp[1][3], ap.y, bp3);
        }
        __syncthreads();
    }

    // epilogue: write g_xw2[dir][s][col(u,q)][b]
#pragma unroll
    for (int j = 0; j < 4; j++) {
        const int g   = n0 + tx * 4 + j;
        const int dir = g >> 11;
        const int gl  = g & 2047;
        const int q   = gl >> 9;
        const int u   = gl & 511;
        const int col = (u >> 1) * 8 + q * 2 + (u & 1);
        const float bias = dir ? b_b[gl] : b_f[gl];
#pragma unroll
        for (int p = 0; p < 2; p++) {
            float2 v = unpack2(accp[p][j]);
            const int mA = m0 + ty * 4 + 2 * p;
            g_xw2[dir][mA >> 6][col][mA & 63]             = v.x + bias;
            g_xw2[dir][(mA + 1) >> 6][col][(mA + 1) & 63] = v.y + bias;
        }
    }
}

// ---------------- K2: one LSTM time step (weights-in-smem-once, direct-LDG h) -------
// grid (128, 2): blockIdx.y = dir, blockIdx.x = slice of 4 units. 128 threads:
// pp = tid>>6 (unit pair), j = tid&63 (batch). 2 CTAs/SM. The CTA's full-step
// weight slice (512 k x 16 cols = 32 KB) is staged into smem ONCE (one sync);
// h is read straight from the k-major carry via __ldg (1 wf/k, L1-served).
// No per-tile staging, no double buffer, no per-tile barriers.
__global__ __launch_bounds__(128, 2) void k2_step(const int* __restrict__ lengths, int t)
{
    __shared__ float ws[512][16];   // [k][pp*8 + gate*2 + unit]  32 KB

    const int dir   = blockIdx.y;
    const int s     = dir ? (SS - 1 - t) : t;
    const int slice = blockIdx.x;          // 0..127
    const int tid = threadIdx.x;
    const int pp  = tid >> 6;              // unit pair within slice
    const int j   = tid & 63;              // batch
    const int u0  = slice * 4 + 2 * pp;    // first unit of pair

    const int len = lengths[j];

    // xw gates: 8 coalesced loads (col stride 64 floats, lanes span b)
    float xwv[8];
    {
        const float* xp = &g_xw2[dir][s][(slice * 2 + pp) * 8][j];
#pragma unroll
        for (int i = 0; i < 8; i++) xwv[i] = __ldg(&xp[i * BB]);
    }

    unsigned long long accI = 0, accF = 0, accG = 0, accO = 0;   // (u0, u0+1)

    if (t > 0) {
        // stage the whole step's weights once (coalesced float4)
        {
            const float* wsrc = &g_wp[dir][0][slice * 16];   // row stride G4
#pragma unroll
            for (int i = 0; i < 16; i++) {
                const int chunk = tid + i * 128;             // 2048 float4 chunks
                const int r = chunk >> 2, c = (chunk & 3) * 4;
                *(float4*)&ws[r][c] = *(const float4*)&wsrc[(long)r * G4 + c];
            }
        }
        __syncthreads();

        const int rp = (t & 1) ^ 1;
        const float* __restrict__ hsrc = &g_ht[dir][rp][0][0];   // [k][b]

        for (int kt = 0; kt < 32; ++kt) {
#pragma unroll
            for (int kk = 0; kk < 16; ++kk) {
                const int k = kt * 16 + kk;
                const float h = __ldg(&hsrc[k * BB + j]);            // 1-wf LDG
                const unsigned long long hp = pack2(h, h);
                ulonglong2 w01 = *(const ulonglong2*)&ws[k][pp * 8];      // broadcast
                ulonglong2 w23 = *(const ulonglong2*)&ws[k][pp * 8 + 4];  // broadcast
                fma2(accI, w01.x, hp);
                fma2(accF, w01.y, hp);
                fma2(accG, w23.x, hp);
                fma2(accO, w23.y, hp);
            }
        }
    }

    // cell update: 2 units x 1 batch, thread-local
    const float2 ai = unpack2(accI), af = unpack2(accF);
    const float2 ag = unpack2(accG), ao = unpack2(accO);

    const float i0 = ai.x + xwv[0], i1 = ai.y + xwv[1];
    const float f0 = af.x + xwv[2], f1 = af.y + xwv[3];
    const float g0 = ag.x + xwv[4], g1 = ag.y + xwv[5];
    const float o0 = ao.x + xwv[6], o1 = ao.y + xwv[7];

    float c_old0 = 0.f, c_old1 = 0.f;
    if (t > 0) {
        c_old0 = g_c[dir][u0][j];
        c_old1 = g_c[dir][u0 + 1][j];
    }
    const float cn0 = sigmf(f0) * c_old0 + sigmf(i0) * tanhf(g0);
    const float hn0 = sigmf(o0) * tanhf(cn0);
    const float cn1 = sigmf(f1) * c_old1 + sigmf(i1) * tanhf(g1);
    const float hn1 = sigmf(o1) * tanhf(cn1);

    const bool msk = s < len;
    const float hw0 = msk ? hn0 : 0.f;
    const float hw1 = msk ? hn1 : 0.f;
    g_c[dir][u0][j]     = msk ? cn0 : c_old0;      // coalesced over b
    g_c[dir][u0 + 1][j] = msk ? cn1 : c_old1;
    const int wp = t & 1;
    g_ht[dir][wp][u0][j]     = hw0;                // coalesced k-major carry
    g_ht[dir][wp][u0 + 1][j] = hw1;
    *(float2*)&g_hbk[s][dir][j][u0] = make_float2(hw0, hw1);   // K3 layout (once/step)
}

// ---------------- K3: emissions feats = h @ w_out^T + b_out ----------------
__global__ __launch_bounds__(256) void k3_feats(
    const float* __restrict__ w_out, const float* __restrict__ b_out)
{
    __shared__ float ws[TT * 1024];   // [t][dir*512 + k]
    for (int i = threadIdx.x; i < TT * 1024; i += 256) ws[i] = w_out[i];
    __syncthreads();

    const int widx = blockIdx.x * 8 + (threadIdx.x >> 5);
    const int lane = threadIdx.x & 31;
    const int s = widx >> 6, b = widx & 63;

    float acc[TT];
#pragma unroll
    for (int t = 0; t < TT; t++) acc[t] = 0.0f;

#pragma unroll
    for (int d = 0; d < 2; d++) {
        const float* hrow = &g_hbk[s][d][b][0];
#pragma unroll 4
        for (int i = 0; i < 16; i++) {
            const int k = lane + i * 32;
            const float hv = hrow[k];
#pragma unroll
            for (int t = 0; t < TT; t++) acc[t] += hv * ws[t * 1024 + d * 512 + k];
        }
    }
#pragma unroll
    for (int t = 0; t < TT; t++) {
        float v = acc[t];
        v += __shfl_xor_sync(0xffffffffu, v, 16);
        v += __shfl_xor_sync(0xffffffffu, v, 8);
        v += __shfl_xor_sync(0xffffffffu, v, 4);
        v += __shfl_xor_sync(0xffffffffu, v, 2);
        v += __shfl_xor_sync(0xffffffffu, v, 1);
        if (lane == t) g_feats[b][s][t] = v + b_out[t];
    }
}

// ---------------- K4: Viterbi decode + backtrace (one warp per batch) ----------------
// Output written as float32 (harness __output__ dtype).
__global__ __launch_bounds__(32) void k4_viterbi(
    const float* __restrict__ start_t, const float* __restrict__ end_t,
    const float* __restrict__ trans, const int* __restrict__ lengths,
    float* __restrict__ out)
{
    const int b = blockIdx.x;
    const int lane = threadIdx.x;
    __shared__ float fe[SS][TT];
    __shared__ float tr[TT][TT];
    __shared__ float sc[TT];
    __shared__ unsigned char bp[SS][TT];

    for (int i = lane; i < SS * TT; i += 32)
        ((float*)fe)[i] = ((const float*)g_feats[b])[i];
    for (int i = lane; i < TT * TT; i += 32)
        ((float*)tr)[i] = trans[i];
    int len = lengths[b];
    if (len < 0) len = 0; if (len > SS) len = SS;
    __syncwarp();
    if (lane < TT) sc[lane] = start_t[lane] + fe[0][lane];
    __syncwarp();

    for (int s = 1; s < SS; ++s) {
        float best = -1e30f; int arg = 0;
        if (lane < TT) {
#pragma unroll
            for (int i = 0; i < TT; i++) {
                const float c = sc[i] + tr[i][lane];
                if (c > best) { best = c; arg = i; }   // first-max, matches jnp.argmax
            }
        }
        __syncwarp();
        if (lane < TT) {
            if (s < len) { sc[lane] = best + fe[s][lane]; bp[s][lane] = (unsigned char)arg; }
            else         { bp[s][lane] = (unsigned char)lane; }
        }
        __syncwarp();
    }

    if (lane == 0) {
        float bestv = -1e30f; int last = 0;
        for (int j = 0; j < TT; j++) {
            const float v = sc[j] + end_t[j];
            if (v > bestv) { bestv = v; last = j; }
        }
        int cur = last;
        for (int s = SS - 1; s >= 1; --s) {
            out[b * SS + s] = (float)((s < len) ? cur : 0);
            cur = bp[s][cur];
        }
        out[b * SS + 0] = (float)cur;
    }
}

// ---------------- host ----------------
static int find_slot(const int* sz, int n, int want, int which, int fallback) {
    int seen = 0;
    for (int i = 0; i < n; i++)
        if (sz[i] == want) { if (seen == which) return i; seen++; }
    return fallback;
}

extern "C" void kernel_launch(void* const* d_in, const int* in_sizes, int n_in,
                              void* d_out, int out_size)
{
    const int i_tok  = find_slot(in_sizes, n_in, SS * BB,      0, 0);
    const int i_len  = find_slot(in_sizes, n_in, BB,           0, 1);
    const int i_emb  = find_slot(in_sizes, n_in, 30000 * EE,   0, 2);
    const int i_wif  = find_slot(in_sizes, n_in, G4 * EE,      0, 3);
    const int i_whf  = find_slot(in_sizes, n_in, G4 * HH,      0, 4);
    const int i_bf   = find_slot(in_sizes, n_in, G4,           0, 5);
    const int i_wib  = find_slot(in_sizes, n_in, G4 * EE,      1, 6);
    const int i_whb  = find_slot(in_sizes, n_in, G4 * HH,      1, 7);
    const int i_bb   = find_slot(in_sizes, n_in, G4,           1, 8);
    const int i_wout = find_slot(in_sizes, n_in, TT * 2 * HH,  0, 9);
    const int i_bout = find_slot(in_sizes, n_in, TT,           0, 10);
    const int i_st   = find_slot(in_sizes, n_in, TT,           1, 11);
    const int i_en   = find_slot(in_sizes, n_in, TT,           2, 12);
    const int i_tr   = find_slot(in_sizes, n_in, TT * TT,      0, 13);

    const int*   tokens  = (const int*)  d_in[i_tok];
    const int*   lens    = (const int*)  d_in[i_len];
    const float* emb     = (const float*)d_in[i_emb];
    const float* wih_f   = (const float*)d_in[i_wif];
    const float* whh_f   = (const float*)d_in[i_whf];
    const float* b_f     = (const float*)d_in[i_bf];
    const float* wih_b   = (const float*)d_in[i_wib];
    const float* whh_b   = (const float*)d_in[i_whb];
    const float* b_b     = (const float*)d_in[i_bb];
    const float* w_out   = (const float*)d_in[i_wout];
    const float* b_out   = (const float*)d_in[i_bout];
    const float* start_t = (const float*)d_in[i_st];
    const float* end_t   = (const float*)d_in[i_en];
    const float* trans   = (const float*)d_in[i_tr];
    float* out = (float*)d_out;

    k0_prep<<<dim3(2, HH), HH>>>(whh_f, whh_b);
    k1_proj<<<dim3(64, 256), 256>>>(tokens, emb, wih_f, b_f, wih_b, b_b);
    for (int t = 0; t < SS; ++t)
        k2_step<<<dim3(128, 2), 128>>>(lens, t);
    k3_feats<<<2048, 256>>>(w_out, b_out);
    k4_viterbi<<<64, 32>>>(start_t, end_t, trans, lens, out);
}

// round 12
// speedup vs baseline: 1.2393x; 1.0446x over previous
#include <cuda_runtime.h>
#include <math.h>

#define SS 256
#define BB 64
#define HH 512
#define EE 300
#define TT 10
#define G4 2048   // 4*H

// ---------------- scratch (static device memory; no allocations) ----------------
__device__ float g_xw2[2][SS][G4][BB];     // input projections, [dir][s][col][b] (268 MB)
__device__ float g_hbk[SS][2][BB][HH];     // h outputs [s][dir][b][k] for K3 (134 MB)
__device__ float g_ht[2][2][HH][BB];       // [dir][parity][k][b] k-major carry (L2-hot)
__device__ float g_c[2][HH][BB];           // c carry [dir][u][b]
__device__ float g_wp[2][HH][G4];          // permuted whh: [d][k][(u>>1)*8+q*2+(u&1)] (8 MB)
__device__ float g_feats[BB][SS][TT];      // emissions

__device__ __forceinline__ float sigmf(float x) { return 1.0f / (1.0f + expf(-x)); }

// ---- packed f32x2 helpers (FFMA2: 2 independent fp32 FMAs, bit-exact) ----
__device__ __forceinline__ unsigned long long pack2(float lo, float hi) {
    unsigned long long r;
    asm("mov.b64 %0, {%1, %2};" : "=l"(r) : "f"(lo), "f"(hi));
    return r;
}
__device__ __forceinline__ void fma2(unsigned long long& d, unsigned long long a, unsigned long long b) {
    asm("fma.rn.f32x2 %0, %1, %2, %0;" : "+l"(d) : "l"(a), "l"(b));
}
__device__ __forceinline__ float2 unpack2(unsigned long long v) {
    float lo, hi;
    asm("mov.b64 {%0, %1}, %2;" : "=f"(lo), "=f"(hi) : "l"(v));
    return make_float2(lo, hi);
}

// ---------------- K0: permute recurrent weights ----------------
// g_wp[d][k][(u>>1)*8 + q*2 + (u&1)] = whh_d[q*HH + u][k]
__global__ void k0_prep(const float* __restrict__ whh_f, const float* __restrict__ whh_b) {
    const int d = blockIdx.x;
    const int k = blockIdx.y;
    const int u = threadIdx.x;    // 0..511
    const float* w = d ? whh_b : whh_f;
    const int colb = (u >> 1) * 8 + (u & 1);
#pragma unroll
    for (int q = 0; q < 4; q++)
        g_wp[d][k][colb + q * 2] = w[(q * HH + u) * HH + k];
}

// ---------------- K1: fused embedding gather + input projection GEMM ----------------
__global__ __launch_bounds__(256) void k1_proj(
    const int* __restrict__ tokens, const float* __restrict__ emb,
    const float* __restrict__ wih_f, const float* __restrict__ b_f,
    const float* __restrict__ wih_b, const float* __restrict__ b_b)
{
    __shared__ float As[20][68];   // [k][m-local]
    __shared__ float Bs[20][68];   // [k][n-local]

    const int tid = threadIdx.x;
    const int tx = tid & 15, ty = tid >> 4;
    const int n0 = blockIdx.x * 64;
    const int m0 = blockIdx.y * 64;

    const int arow = tid >> 2;            // 0..63
    const int akk  = (tid & 3) * 5;       // 0,5,10,15
    const int m_g  = m0 + arow;
    const int s_g  = m_g >> 6, b_g = m_g & 63;
    int tok = tokens[b_g * SS + s_g];
    if (tok < 0 || tok >= 30000) tok = 0;
    const float* asrc = emb + (long)tok * EE;

    const int bg = n0 + arow;
    const float* wsrc = (bg < G4) ? (wih_f + (long)bg * EE)
                                  : (wih_b + (long)(bg - G4) * EE);

    unsigned long long accp[2][4] = {};

    for (int kt = 0; kt < 15; ++kt) {     // K = 300 = 15 * 20
        const int k0 = kt * 20;
#pragma unroll
        for (int l = 0; l < 5; l++) As[akk + l][arow] = asrc[k0 + akk + l];
#pragma unroll
        for (int l = 0; l < 5; l++) Bs[akk + l][arow] = wsrc[k0 + akk + l];
        __syncthreads();
#pragma unroll
        for (int k = 0; k < 20; k++) {
            ulonglong2 ap = *(const ulonglong2*)&As[k][ty * 4];
            float4 bv = *(const float4*)&Bs[k][tx * 4];
            unsigned long long bp0 = pack2(bv.x, bv.x);
            unsigned long long bp1 = pack2(bv.y, bv.y);
            unsigned long long bp2 = pack2(bv.z, bv.z);
            unsigned long long bp3 = pack2(bv.w, bv.w);
            fma2(accp[0][0], ap.x, bp0); fma2(accp[0][1], ap.x, bp1);
            fma2(accp[0][2], ap.x, bp2); fma2(accp[0][3], ap.x, bp3);
            fma2(accp[1][0], ap.y, bp0); fma2(accp[1][1], ap.y, bp1);
            fma2(accp[1][2], ap.y, bp2); fma2(accp[1][3], ap.y, bp3);
        }
        __syncthreads();
    }

    // epilogue: write g_xw2[dir][s][col(u,q)][b]
#pragma unroll
    for (int j = 0; j < 4; j++) {
        const int g   = n0 + tx * 4 + j;
        const int dir = g >> 11;
        const int gl  = g & 2047;
        const int q   = gl >> 9;
        const int u   = gl & 511;
        const int col = (u >> 1) * 8 + q * 2 + (u & 1);
        const float bias = dir ? b_b[gl] : b_f[gl];
#pragma unroll
        for (int p = 0; p < 2; p++) {
            float2 v = unpack2(accp[p][j]);
            const int mA = m0 + ty * 4 + 2 * p;
            g_xw2[dir][mA >> 6][col][mA & 63]             = v.x + bias;
            g_xw2[dir][(mA + 1) >> 6][col][(mA + 1) & 63] = v.y + bias;
        }
    }
}

// ---------------- K2: one LSTM time step (K-split halves, 512-thread CTAs) ----------
// grid (64, 2): blockIdx.y = dir, blockIdx.x = group of 8 units (4 pairs).
// 512 threads: kh = tid>>8 (K half), pp = (tid>>6)&3 (unit pair), j = tid&63 (batch).
// 128 CTAs <= 148 SMs -> wave-1, perfectly balanced, 4 warps/SMSP.
// Weights (64 KB) staged once per step; h via direct 1-wf __ldg from k-major carry.
// Cross-half reduction through padded smem, fixed order (half0+half1)+xw.
__global__ __launch_bounds__(512, 1) void k2_step(const int* __restrict__ lengths, int t)
{
    __shared__ float ws[512][32];     // [k][pp*8 + gate*2 + unit]  64 KB
    __shared__ float red[4][64][9];   // [pp][j][8 partials, pad 9]  9 KB

    const int dir = blockIdx.y;
    const int s   = dir ? (SS - 1 - t) : t;
    const int bx  = blockIdx.x;            // 0..63
    const int tid = threadIdx.x;
    const int kh  = tid >> 8;              // K half
    const int pp  = (tid >> 6) & 3;        // pair in group
    const int j   = tid & 63;              // batch
    const int pg  = bx * 4 + pp;           // global unit pair
    const int u0  = pg * 2;

    const int len = lengths[j];

    // xw gates (kh==0 lanes only; coalesced over b)
    float xwv[8];
    if (kh == 0) {
        const float* xp = &g_xw2[dir][s][pg * 8][j];
#pragma unroll
        for (int i = 0; i < 8; i++) xwv[i] = __ldg(&xp[i * BB]);
    }

    unsigned long long accI = 0, accF = 0, accG = 0, accO = 0;   // (u0, u0+1)

    if (t > 0) {
        // stage the whole step's weights once (cols [bx*32, bx*32+32), all 512 k)
        {
            const float* wsrc = &g_wp[dir][0][bx * 32];   // row stride G4
#pragma unroll
            for (int i = 0; i < 8; i++) {
                const int chunk = tid + i * 512;          // 4096 float4 chunks
                const int r = chunk >> 3, c = (chunk & 7) * 4;
                *(float4*)&ws[r][c] = *(const float4*)&wsrc[(long)r * G4 + c];
            }
        }
        __syncthreads();

        const int rp = (t & 1) ^ 1;
        const float* __restrict__ hsrc = &g_ht[dir][rp][kh * 256][0];   // this half's rows

        for (int kt = 0; kt < 16; ++kt) {
#pragma unroll
            for (int kk = 0; kk < 16; ++kk) {
                const int k = kt * 16 + kk;
                const float h = __ldg(&hsrc[k * BB + j]);                // 1-wf LDG (L2)
                const unsigned long long hp = pack2(h, h);
                const int kw = kh * 256 + k;
                ulonglong2 w01 = *(const ulonglong2*)&ws[kw][pp * 8];       // broadcast
                ulonglong2 w23 = *(const ulonglong2*)&ws[kw][pp * 8 + 4];   // broadcast
                fma2(accI, w01.x, hp);
                fma2(accF, w01.y, hp);
                fma2(accG, w23.x, hp);
                fma2(accO, w23.y, hp);
            }
        }
    }

    // cross-half reduction (fixed order: half0 + half1 -> deterministic)
    const float2 ai = unpack2(accI), af = unpack2(accF);
    const float2 ag = unpack2(accG), ao = unpack2(accO);
    if (kh == 1) {
        red[pp][j][0] = ai.x; red[pp][j][1] = ai.y;
        red[pp][j][2] = af.x; red[pp][j][3] = af.y;
        red[pp][j][4] = ag.x; red[pp][j][5] = ag.y;
        red[pp][j][6] = ao.x; red[pp][j][7] = ao.y;
    }
    __syncthreads();
    if (kh == 0) {
        const float i0 = (ai.x + red[pp][j][0]) + xwv[0];
        const float i1 = (ai.y + red[pp][j][1]) + xwv[1];
        const float f0 = (af.x + red[pp][j][2]) + xwv[2];
        const float f1 = (af.y + red[pp][j][3]) + xwv[3];
        const float g0 = (ag.x + red[pp][j][4]) + xwv[4];
        const float g1 = (ag.y + red[pp][j][5]) + xwv[5];
        const float o0 = (ao.x + red[pp][j][6]) + xwv[6];
        const float o1 = (ao.y + red[pp][j][7]) + xwv[7];

        float c_old0 = 0.f, c_old1 = 0.f;
        if (t > 0) {
            c_old0 = g_c[dir][u0][j];
            c_old1 = g_c[dir][u0 + 1][j];
        }
        const float cn0 = sigmf(f0) * c_old0 + sigmf(i0) * tanhf(g0);
        const float hn0 = sigmf(o0) * tanhf(cn0);
        const float cn1 = sigmf(f1) * c_old1 + sigmf(i1) * tanhf(g1);
        const float hn1 = sigmf(o1) * tanhf(cn1);

        const bool msk = s < len;
        const float hw0 = msk ? hn0 : 0.f;
        const float hw1 = msk ? hn1 : 0.f;
        g_c[dir][u0][j]     = msk ? cn0 : c_old0;      // coalesced over b
        g_c[dir][u0 + 1][j] = msk ? cn1 : c_old1;
        const int wp = t & 1;
        g_ht[dir][wp][u0][j]     = hw0;                // coalesced k-major carry
        g_ht[dir][wp][u0 + 1][j] = hw1;
        *(float2*)&g_hbk[s][dir][j][u0] = make_float2(hw0, hw1);   // K3 layout
    }
}

// ---------------- K3: emissions feats = h @ w_out^T + b_out ----------------
__global__ __launch_bounds__(256) void k3_feats(
    const float* __restrict__ w_out, const float* __restrict__ b_out)
{
    __shared__ float ws[TT * 1024];   // [t][dir*512 + k]
    for (int i = threadIdx.x; i < TT * 1024; i += 256) ws[i] = w_out[i];
    __syncthreads();

    const int widx = blockIdx.x * 8 + (threadIdx.x >> 5);
    const int lane = threadIdx.x & 31;
    const int s = widx >> 6, b = widx & 63;

    float acc[TT];
#pragma unroll
    for (int t = 0; t < TT; t++) acc[t] = 0.0f;

#pragma unroll
    for (int d = 0; d < 2; d++) {
        const float* hrow = &g_hbk[s][d][b][0];
#pragma unroll 4
        for (int i = 0; i < 16; i++) {
            const int k = lane + i * 32;
            const float hv = hrow[k];
#pragma unroll
            for (int t = 0; t < TT; t++) acc[t] += hv * ws[t * 1024 + d * 512 + k];
        }
    }
#pragma unroll
    for (int t = 0; t < TT; t++) {
        float v = acc[t];
        v += __shfl_xor_sync(0xffffffffu, v, 16);
        v += __shfl_xor_sync(0xffffffffu, v, 8);
        v += __shfl_xor_sync(0xffffffffu, v, 4);
        v += __shfl_xor_sync(0xffffffffu, v, 2);
        v += __shfl_xor_sync(0xffffffffu, v, 1);
        if (lane == t) g_feats[b][s][t] = v + b_out[t];
    }
}

// ---------------- K4: Viterbi decode + backtrace (one warp per batch) ----------------
// Output written as float32 (harness __output__ dtype).
__global__ __launch_bounds__(32) void k4_viterbi(
    const float* __restrict__ start_t, const float* __restrict__ end_t,
    const float* __restrict__ trans, const int* __restrict__ lengths,
    float* __restrict__ out)
{
    const int b = blockIdx.x;
    const int lane = threadIdx.x;
    __shared__ float fe[SS][TT];
    __shared__ float tr[TT][TT];
    __shared__ float sc[TT];
    __shared__ unsigned char bp[SS][TT];

    for (int i = lane; i < SS * TT; i += 32)
        ((float*)fe)[i] = ((const float*)g_feats[b])[i];
    for (int i = lane; i < TT * TT; i += 32)
        ((float*)tr)[i] = trans[i];
    int len = lengths[b];
    if (len < 0) len = 0; if (len > SS) len = SS;
    __syncwarp();
    if (lane < TT) sc[lane] = start_t[lane] + fe[0][lane];
    __syncwarp();

    for (int s = 1; s < SS; ++s) {
        float best = -1e30f; int arg = 0;
        if (lane < TT) {
#pragma unroll
            for (int i = 0; i < TT; i++) {
                const float c = sc[i] + tr[i][lane];
                if (c > best) { best = c; arg = i; }   // first-max, matches jnp.argmax
            }
        }
        __syncwarp();
        if (lane < TT) {
            if (s < len) { sc[lane] = best + fe[s][lane]; bp[s][lane] = (unsigned char)arg; }
            else         { bp[s][lane] = (unsigned char)lane; }
        }
        __syncwarp();
    }

    if (lane == 0) {
        float bestv = -1e30f; int last = 0;
        for (int j = 0; j < TT; j++) {
            const float v = sc[j] + end_t[j];
            if (v > bestv) { bestv = v; last = j; }
        }
        int cur = last;
        for (int s = SS - 1; s >= 1; --s) {
            out[b * SS + s] = (float)((s < len) ? cur : 0);
            cur = bp[s][cur];
        }
        out[b * SS + 0] = (float)cur;
    }
}

// ---------------- host ----------------
static int find_slot(const int* sz, int n, int want, int which, int fallback) {
    int seen = 0;
    for (int i = 0; i < n; i++)
        if (sz[i] == want) { if (seen == which) return i; seen++; }
    return fallback;
}

extern "C" void kernel_launch(void* const* d_in, const int* in_sizes, int n_in,
                              void* d_out, int out_size)
{
    const int i_tok  = find_slot(in_sizes, n_in, SS * BB,      0, 0);
    const int i_len  = find_slot(in_sizes, n_in, BB,           0, 1);
    const int i_emb  = find_slot(in_sizes, n_in, 30000 * EE,   0, 2);
    const int i_wif  = find_slot(in_sizes, n_in, G4 * EE,      0, 3);
    const int i_whf  = find_slot(in_sizes, n_in, G4 * HH,      0, 4);
    const int i_bf   = find_slot(in_sizes, n_in, G4,           0, 5);
    const int i_wib  = find_slot(in_sizes, n_in, G4 * EE,      1, 6);
    const int i_whb  = find_slot(in_sizes, n_in, G4 * HH,      1, 7);
    const int i_bb   = find_slot(in_sizes, n_in, G4,           1, 8);
    const int i_wout = find_slot(in_sizes, n_in, TT * 2 * HH,  0, 9);
    const int i_bout = find_slot(in_sizes, n_in, TT,           0, 10);
    const int i_st   = find_slot(in_sizes, n_in, TT,           1, 11);
    const int i_en   = find_slot(in_sizes, n_in, TT,           2, 12);
    const int i_tr   = find_slot(in_sizes, n_in, TT * TT,      0, 13);

    const int*   tokens  = (const int*)  d_in[i_tok];
    const int*   lens    = (const int*)  d_in[i_len];
    const float* emb     = (const float*)d_in[i_emb];
    const float* wih_f   = (const float*)d_in[i_wif];
    const float* whh_f   = (const float*)d_in[i_whf];
    const float* b_f     = (const float*)d_in[i_bf];
    const float* wih_b   = (const float*)d_in[i_wib];
    const float* whh_b   = (const float*)d_in[i_whb];
    const float* b_b     = (const float*)d_in[i_bb];
    const float* w_out   = (const float*)d_in[i_wout];
    const float* b_out   = (const float*)d_in[i_bout];
    const float* start_t = (const float*)d_in[i_st];
    const float* end_t   = (const float*)d_in[i_en];
    const float* trans   = (const float*)d_in[i_tr];
    float* out = (float*)d_out;

    k0_prep<<<dim3(2, HH), HH>>>(whh_f, whh_b);
    k1_proj<<<dim3(64, 256), 256>>>(tokens, emb, wih_f, b_f, wih_b, b_b);
    for (int t = 0; t < SS; ++t)
        k2_step<<<dim3(64, 2), 512>>>(lens, t);
    k3_feats<<<2048, 256>>>(w_out, b_out);
    k4_viterbi<<<64, 32>>>(start_t, end_t, trans, lens, out);
}